// round 5
// baseline (speedup 1.0000x reference)
#include <cuda_runtime.h>

// CRF NLL, prob-domain forward. B=64, S=512, T=64 (START=62, END=63).
// R5: one warp per batch, warp-synchronous (no block barriers in loop),
//     packed f32x2 FFMA with duplicated-pair p storage, exact power-of-2
//     renorm every 8 steps. 8 warps/CTA (2 per SMSP), grid=8.
//
// Inputs: d_in[0] feats f32 [B,S,T], d_in[1] transitions f32 [T,T],
//         d_in[2] mask i32 [B,S] (contiguous prefix), d_in[3] tags i32 [B,S]
// Output: f32 scalar sum_b (forward_b - gold_b)

#define B_    64
#define S_    512
#define T_    64
#define CHUNK 8
#define WPC   8     // warps (batches) per CTA

__device__ float g_res[B_];

__global__ __launch_bounds__(WPC * 32, 1) void crf_forward_kernel(
    const float* __restrict__ feats,
    const float* __restrict__ trans,
    const int*   __restrict__ mask,
    const int*   __restrict__ tags)
{
    __shared__ __align__(16) float trans_sh[T_ * T_];
    __shared__ __align__(16) float p_sh[WPC][2][2 * T_];   // duplicated pairs

    const int tid  = threadIdx.x;
    const int lane = tid & 31;
    const int wid  = tid >> 5;
    const int c0   = 2 * lane;            // my two state columns: c0, c0+1
    const int b    = blockIdx.x * WPC + wid;

    const float* fb    = feats + (size_t)b * S_ * T_;
    const int*   maskb = mask  + b * S_;
    const int*   tagsb = tags  + b * S_;

    // ---- stage transitions (coalesced float4) ----
    {
        const float4* t4 = (const float4*)trans;
        float4*       s4 = (float4*)trans_sh;
        #pragma unroll
        for (int i = 0; i < 4; ++i) s4[i * 256 + tid] = t4[i * 256 + tid];
    }
    __syncthreads();   // only block-wide barrier

    // ---- per-warp length ----
    int len = 0;
    #pragma unroll
    for (int k = 0; k < 16; ++k) len += maskb[lane + 32 * k];
    #pragma unroll
    for (int o = 16; o; o >>= 1) len += __shfl_xor_sync(0xffffffffu, len, o);

    // ---- gold path score (one-time, per warp) ----
    float gs = 0.f;
    #pragma unroll
    for (int k = 0; k < 16; ++k) {
        int s = lane + 32 * k;
        if (s < len) {
            int tg = tagsb[s];
            int pv = s ? tagsb[s - 1] : (T_ - 2);
            gs += fb[s * T_ + tg] + trans_sh[pv * T_ + tg];
        }
    }
    if (lane == 0) gs += trans_sh[tagsb[len - 1] * T_ + (T_ - 1)];
    #pragma unroll
    for (int o = 16; o; o >>= 1) gs += __shfl_xor_sync(0xffffffffu, gs, o);

    // ---- E pairs: e[i] = (exp(trans[i][c0]), exp(trans[i][c0+1])) ----
    unsigned long long e[T_];
    #pragma unroll
    for (int i = 0; i < T_; ++i) {
        float a0 = __expf(trans_sh[i * T_ + c0]);
        float a1 = __expf(trans_sh[i * T_ + c0 + 1]);
        asm("mov.b64 %0, {%1, %2};" : "=l"(e[i]) : "f"(a0), "f"(a1));
    }
    // END-transition factors for my columns
    const float et0 = __expf(trans_sh[c0 * T_ + (T_ - 1)]);
    const float et1 = __expf(trans_sh[(c0 + 1) * T_ + (T_ - 1)]);

    // ---- smem p base (duplicated-pair layout) ----
    unsigned pbase = (unsigned)__cvta_generic_to_shared(&p_sh[wid][0][0]);

    // ---- init p_0 (my columns), store duplicated ----
    float q0 = __expf(fb[c0]     + trans_sh[(T_ - 2) * T_ + c0]);
    float q1 = __expf(fb[c0 + 1] + trans_sh[(T_ - 2) * T_ + c0 + 1]);
    int   cur  = 0;
    int   ksum = 0;
    {
        unsigned addr = pbase + 16 * lane;
        asm volatile("st.shared.v4.b32 [%0], {%1,%1,%2,%2};"
                     :: "r"(addr), "f"(q0), "f"(q1) : "memory");
    }
    __syncwarp();

    // ---- prefetch first chunk of emissions (steps 1..8, my columns) ----
    float2 fr[CHUNK], fr2[CHUNK];
    int c = 1;
    #pragma unroll
    for (int k = 0; k < CHUNK; ++k) {
        int s = min(c + k, S_ - 1);
        fr[k] = *(const float2*)(fb + s * T_ + c0);
    }

    // ---- forward recurrence (warp-synchronous) ----
    while (c < len) {
        const int cnt = min(CHUNK, len - c);
        // prefetch next chunk
        {
            int nc = c + CHUNK;
            #pragma unroll
            for (int k = 0; k < CHUNK; ++k) {
                int s = min(nc + k, S_ - 1);
                fr2[k] = *(const float2*)(fb + s * T_ + c0);
            }
        }

        #pragma unroll
        for (int k = 0; k < CHUNK; ++k) {
            if (k >= cnt) break;   // warp-uniform
            float ef0 = __expf(fr[k].x);
            float ef1 = __expf(fr[k].y);

            unsigned pb = pbase + (cur << 9);   // cur * 512 bytes
            unsigned long long acc0 = 0ull, acc1 = 0ull, acc2 = 0ull, acc3 = 0ull;
            #pragma unroll
            for (int m = 0; m < 32; m += 2) {
                unsigned long long pd0, pd1, pd2, pd3;
                asm volatile("ld.shared.v2.b64 {%0,%1}, [%2];"
                             : "=l"(pd0), "=l"(pd1) : "r"(pb + 16 * m));
                asm volatile("ld.shared.v2.b64 {%0,%1}, [%2];"
                             : "=l"(pd2), "=l"(pd3) : "r"(pb + 16 * m + 16));
                asm("fma.rn.f32x2 %0, %1, %2, %0;" : "+l"(acc0) : "l"(pd0), "l"(e[2 * m + 0]));
                asm("fma.rn.f32x2 %0, %1, %2, %0;" : "+l"(acc1) : "l"(pd1), "l"(e[2 * m + 1]));
                asm("fma.rn.f32x2 %0, %1, %2, %0;" : "+l"(acc2) : "l"(pd2), "l"(e[2 * m + 2]));
                asm("fma.rn.f32x2 %0, %1, %2, %0;" : "+l"(acc3) : "l"(pd3), "l"(e[2 * m + 3]));
            }
            asm("add.rn.f32x2 %0, %0, %1;" : "+l"(acc0) : "l"(acc2));
            asm("add.rn.f32x2 %0, %0, %1;" : "+l"(acc1) : "l"(acc3));
            asm("add.rn.f32x2 %0, %0, %1;" : "+l"(acc0) : "l"(acc1));
            float v0, v1;
            asm("mov.b64 {%0, %1}, %2;" : "=f"(v0), "=f"(v1) : "l"(acc0));

            q0 = v0 * ef0;
            q1 = v1 * ef1;

            if (k == CHUNK - 1) {
                // exact power-of-2 renorm from lane 0's exponent
                int bits = __float_as_int(q0);
                bits = __shfl_sync(0xffffffffu, bits, 0);
                int ke = ((bits >> 23) & 255) - 127;
                float scl = __int_as_float((127 - ke) << 23);
                q0 *= scl;
                q1 *= scl;
                ksum += ke;
            }

            unsigned addr = pbase + ((cur ^ 1) << 9) + 16 * lane;
            asm volatile("st.shared.v4.b32 [%0], {%1,%1,%2,%2};"
                         :: "r"(addr), "f"(q0), "f"(q1) : "memory");
            __syncwarp();
            cur ^= 1;
        }
        #pragma unroll
        for (int k = 0; k < CHUNK; ++k) fr[k] = fr2[k];
        c += cnt;
    }

    // ---- final transition into END ----
    float w = q0 * et0 + q1 * et1;
    #pragma unroll
    for (int o = 16; o; o >>= 1) w += __shfl_xor_sync(0xffffffffu, w, o);
    if (lane == 0) {
        float forward = (float)ksum * 0.69314718055994531f + __logf(w);
        g_res[b] = forward - gs;
    }
}

__global__ void crf_reduce_kernel(float* __restrict__ out)
{
    const int tid  = threadIdx.x;
    const int lane = tid & 31;
    const int warp = tid >> 5;
    __shared__ float sh[2];

    float v = g_res[tid];
    #pragma unroll
    for (int o = 16; o; o >>= 1) v += __shfl_xor_sync(0xffffffffu, v, o);
    if (lane == 0) sh[warp] = v;
    __syncthreads();
    if (tid == 0) out[0] = sh[0] + sh[1];
}

extern "C" void kernel_launch(void* const* d_in, const int* in_sizes, int n_in,
                              void* d_out, int out_size)
{
    const float* feats = (const float*)d_in[0];
    const float* trans = (const float*)d_in[1];
    const int*   mask  = (const int*)d_in[2];
    const int*   tags  = (const int*)d_in[3];
    float* out = (float*)d_out;

    crf_forward_kernel<<<B_ / WPC, WPC * 32>>>(feats, trans, mask, tags);
    crf_reduce_kernel<<<1, 64>>>(out);
}

// round 6
// speedup vs baseline: 1.2783x; 1.2783x over previous
#include <cuda_runtime.h>

// CRF NLL, prob-domain forward with chunked renormalization.
// B=64, S=512, T=64 (62 tags + START=62 + END=63).
// R6: 128 threads/CTA, i-contraction split 2 ways (one SHFL_XOR(16)),
//     1 warp per SMSP, 1 barrier per step. Grid = 64.
//
// Inputs: d_in[0] feats f32 [B,S,T], d_in[1] transitions f32 [T,T],
//         d_in[2] mask i32 [B,S] (contiguous prefix), d_in[3] tags i32 [B,S]
// Output: f32 scalar sum_b (forward_b - gold_b)

#define B_    64
#define S_    512
#define T_    64
#define CHUNK 8

__device__ float g_res[B_];

__global__ __launch_bounds__(128, 1) void crf_forward_kernel(
    const float* __restrict__ feats,
    const float* __restrict__ trans,
    const int*   __restrict__ mask,
    const int*   __restrict__ tags)
{
    __shared__ __align__(16) float trans_sh[T_ * T_];
    __shared__ __align__(16) float p_sh[2][T_];
    __shared__ __align__(16) float f_sh[CHUNK][T_];
    __shared__ int   tags_sh[S_];
    __shared__ float redg[4];
    __shared__ float redf[2];
    __shared__ int   redi[4];

    const int b    = blockIdx.x;
    const int tid  = threadIdx.x;
    const int lane = tid & 31;
    const int warp = tid >> 5;                    // 0..3
    const int seg  = lane >> 4;                   // 0..1 : i-segment of 32
    const int j    = (warp << 4) | (lane & 15);   // 0..63 : state column
    const int r    = tid >> 6;                    // 0..1 : staging row group
    const int col  = tid & 63;                    // staging column

    const float* fb    = feats + (size_t)b * S_ * T_;
    const int*   maskb = mask  + b * S_;
    const int*   tagsb = tags  + b * S_;

    // ---- stage transitions (coalesced float4: 1024 float4 / 128 thr) ----
    {
        const float4* t4 = (const float4*)trans;
        float4*       s4 = (float4*)trans_sh;
        #pragma unroll
        for (int i = 0; i < 8; ++i) s4[i * 128 + tid] = t4[i * 128 + tid];
    }
    // ---- tags + length ----
    int lenp = 0;
    #pragma unroll
    for (int k = 0; k < 4; ++k) {
        tags_sh[k * 128 + tid] = tagsb[k * 128 + tid];
        lenp += maskb[k * 128 + tid];
    }
    #pragma unroll
    for (int o = 16; o; o >>= 1) lenp += __shfl_xor_sync(0xffffffffu, lenp, o);
    if (lane == 0) redi[warp] = lenp;
    __syncthreads();
    const int len = redi[0] + redi[1] + redi[2] + redi[3];

    // ---- gold path score ----
    float g = 0.f;
    #pragma unroll
    for (int kk = 0; kk < 4; ++kk) {
        int s = kk * 128 + tid;
        if (s < len) {
            int tg = tags_sh[s];
            int pv = s ? tags_sh[s - 1] : (T_ - 2);
            g += fb[s * T_ + tg] + trans_sh[pv * T_ + tg];
        }
    }
    if (tid == 0) g += trans_sh[tags_sh[len - 1] * T_ + (T_ - 1)];
    #pragma unroll
    for (int o = 16; o; o >>= 1) g += __shfl_xor_sync(0xffffffffu, g, o);
    if (lane == 0) redg[warp] = g;

    // ---- E segment into registers: e[rr] = exp(trans[seg*32+rr][j]) ----
    float e[32];
    #pragma unroll
    for (int rr = 0; rr < 32; ++rr)
        e[rr] = __expf(trans_sh[(seg * 32 + rr) * T_ + j]);

    // ---- init p_0 ----
    if (tid < T_)
        p_sh[0][tid] = __expf(fb[tid] + trans_sh[(T_ - 2) * T_ + tid]);

    // ---- prefetch first chunk's feats (rows 1..8): 4 values/thread ----
    int c = 1;
    float fr[4], fr2[4];
    #pragma unroll
    for (int q = 0; q < 4; ++q) {
        int s = min(c + r + 2 * q, S_ - 1);
        fr[q] = fb[s * T_ + col];
    }
    __syncthreads();   // p_sh, redg visible

    // ---- forward recurrence ----
    int   cur    = 0;
    float logacc = 0.f;

    while (c < len) {
        // stage exp(f) for this chunk from prefetched regs
        #pragma unroll
        for (int q = 0; q < 4; ++q)
            f_sh[r + 2 * q][col] = __expf(fr[q]);

        // prefetch next chunk
        int nc = c + CHUNK;
        if (nc < S_) {
            #pragma unroll
            for (int q = 0; q < 4; ++q) {
                int s = min(nc + r + 2 * q, S_ - 1);
                fr2[q] = fb[s * T_ + col];
            }
        }

        // renormalize: z = sum(p) (broadcast LDS, redundant per-thread tree)
        float z;
        {
            const float4* pv4 = (const float4*)p_sh[cur];
            float z0 = 0.f, z1 = 0.f, z2 = 0.f, z3 = 0.f;
            #pragma unroll
            for (int i = 0; i < 16; i += 4) {
                float4 q0 = pv4[i],     q1 = pv4[i + 1];
                float4 q2 = pv4[i + 2], q3 = pv4[i + 3];
                z0 += (q0.x + q0.y) + (q0.z + q0.w);
                z1 += (q1.x + q1.y) + (q1.z + q1.w);
                z2 += (q2.x + q2.y) + (q2.z + q2.w);
                z3 += (q3.x + q3.y) + (q3.z + q3.w);
            }
            z = (z0 + z1) + (z2 + z3);
        }
        float scale = __fdividef(1.0f, z);
        logacc += __logf(z);

        const int cnt = min(CHUNK, len - c);
        __syncthreads();   // f_sh visible; all p reads done

        #pragma unroll
        for (int k = 0; k < CHUNK; ++k) {
            if (k >= cnt) break;   // uniform across block
            float fk = f_sh[k][j];   // off the post-shfl critical path
            const float4* pp4 = (const float4*)(p_sh[cur] + (seg << 5));
            float a0 = 0.f, a1 = 0.f, a2 = 0.f, a3 = 0.f;
            #pragma unroll
            for (int i = 0; i < 8; ++i) {
                float4 pp = pp4[i];
                a0 = fmaf(pp.x, e[4 * i + 0], a0);
                a1 = fmaf(pp.y, e[4 * i + 1], a1);
                a2 = fmaf(pp.z, e[4 * i + 2], a2);
                a3 = fmaf(pp.w, e[4 * i + 3], a3);
            }
            float v = (a0 + a1) + (a2 + a3);
            v += __shfl_xor_sync(0xffffffffu, v, 16);
            float q = v * fk;
            if (k == 0) q *= scale;
            if (seg == 0) p_sh[cur ^ 1][j] = q;
            __syncthreads();
            cur ^= 1;
        }
        #pragma unroll
        for (int q = 0; q < 4; ++q) fr[q] = fr2[q];
        c += CHUNK;
    }

    // ---- final transition into END ----
    if (tid < T_) {
        float v = p_sh[cur][tid] * __expf(trans_sh[tid * T_ + (T_ - 1)]);
        #pragma unroll
        for (int o = 16; o; o >>= 1) v += __shfl_xor_sync(0xffffffffu, v, o);
        if (lane == 0) redf[warp] = v;
    }
    __syncthreads();
    if (tid == 0) {
        float forward = logacc + __logf(redf[0] + redf[1]);
        float gold = redg[0] + redg[1] + redg[2] + redg[3];
        g_res[b] = forward - gold;
    }
}

__global__ void crf_reduce_kernel(float* __restrict__ out)
{
    const int tid  = threadIdx.x;
    const int lane = tid & 31;
    const int warp = tid >> 5;
    __shared__ float sh[2];

    float v = g_res[tid];
    #pragma unroll
    for (int o = 16; o; o >>= 1) v += __shfl_xor_sync(0xffffffffu, v, o);
    if (lane == 0) sh[warp] = v;
    __syncthreads();
    if (tid == 0) out[0] = sh[0] + sh[1];
}

extern "C" void kernel_launch(void* const* d_in, const int* in_sizes, int n_in,
                              void* d_out, int out_size)
{
    const float* feats = (const float*)d_in[0];
    const float* trans = (const float*)d_in[1];
    const int*   mask  = (const int*)d_in[2];
    const int*   tags  = (const int*)d_in[3];
    float* out = (float*)d_out;

    crf_forward_kernel<<<B_, 128>>>(feats, trans, mask, tags);
    crf_reduce_kernel<<<1, 64>>>(out);
}

// round 7
// speedup vs baseline: 2.2351x; 1.7484x over previous
#include <cuda_runtime.h>
#include <cuda_bf16.h>

// CRF NLL, prob-domain forward with chunked renormalization.
// B=64, S=512, T=64 (62 tags + START=62 + END=63).
// R7: R2 structure (256 thr, 4-way i-segment split, 2 SHFL, 1 bar/step)
//     with bf16 state + HFMA2 matvec (halves FMA issue and p-LDS bytes).
//     Renorm scale exactly compensated -> bf16 z-sum is free accuracy-wise.
//
// Inputs: d_in[0] feats f32 [B,S,T], d_in[1] transitions f32 [T,T],
//         d_in[2] mask i32 [B,S] (contiguous prefix), d_in[3] tags i32 [B,S]
// Output: f32 scalar sum_b (forward_b - gold_b)

#define B_    64
#define S_    512
#define T_    64
#define CHUNK 8

__device__ float g_res[B_];

__global__ __launch_bounds__(256, 1) void crf_forward_kernel(
    const float* __restrict__ feats,
    const float* __restrict__ trans,
    const int*   __restrict__ mask,
    const int*   __restrict__ tags)
{
    __shared__ __align__(16) float trans_sh[T_ * T_];
    __shared__ __align__(16) __nv_bfloat162 p_sh[2][T_ / 2];  // 32 pairs (p_2m, p_2m+1)
    __shared__ __align__(16) float f_sh[CHUNK][T_];
    __shared__ int   tags_sh[S_];
    __shared__ float redg[8];
    __shared__ float redf[2];
    __shared__ int   redi[8];

    const int b    = blockIdx.x;
    const int tid  = threadIdx.x;
    const int lane = tid & 31;
    const int warp = tid >> 5;
    const int seg  = lane >> 3;                 // 0..3 : i-segment of 16
    const int j    = (warp << 3) | (lane & 7);  // 0..63 : state column
    const int r    = tid >> 6;                  // 0..3 : staging row group
    const int col  = tid & 63;                  // staging column

    const float* fb    = feats + (size_t)b * S_ * T_;
    const int*   maskb = mask  + b * S_;
    const int*   tagsb = tags  + b * S_;

    // ---- stage transitions (coalesced float4) ----
    {
        const float4* t4 = (const float4*)trans;
        float4*       s4 = (float4*)trans_sh;
        #pragma unroll
        for (int i = 0; i < 4; ++i) s4[i * 256 + tid] = t4[i * 256 + tid];
    }
    // ---- tags + length ----
    int lenp = 0;
    #pragma unroll
    for (int k = 0; k < 2; ++k) {
        tags_sh[k * 256 + tid] = tagsb[k * 256 + tid];
        lenp += maskb[k * 256 + tid];
    }
    #pragma unroll
    for (int o = 16; o; o >>= 1) lenp += __shfl_xor_sync(0xffffffffu, lenp, o);
    if (lane == 0) redi[warp] = lenp;
    __syncthreads();
    int len = 0;
    #pragma unroll
    for (int w = 0; w < 8; ++w) len += redi[w];

    // ---- gold path score ----
    float g = 0.f;
    #pragma unroll
    for (int kk = 0; kk < 2; ++kk) {
        int s = kk * 256 + tid;
        if (s < len) {
            int tg = tags_sh[s];
            int pv = s ? tags_sh[s - 1] : (T_ - 2);
            g += fb[s * T_ + tg] + trans_sh[pv * T_ + tg];
        }
    }
    if (tid == 0) g += trans_sh[tags_sh[len - 1] * T_ + (T_ - 1)];
    #pragma unroll
    for (int o = 16; o; o >>= 1) g += __shfl_xor_sync(0xffffffffu, g, o);
    if (lane == 0) redg[warp] = g;

    // ---- E segment as bf16 pairs: e2[m] = (E[16s+2m][j], E[16s+2m+1][j]) ----
    __nv_bfloat162 e2[8];
    #pragma unroll
    for (int m = 0; m < 8; ++m) {
        int i0 = seg * 16 + 2 * m;
        float x = __expf(trans_sh[i0 * T_ + j]);
        float y = __expf(trans_sh[(i0 + 1) * T_ + j]);
        e2[m] = __floats2bfloat162_rn(x, y);
    }

    // ---- init p_0 (bf16 state) ----
    if (tid < T_) {
        float p0 = __expf(fb[tid] + trans_sh[(T_ - 2) * T_ + tid]);
        ((__nv_bfloat16*)p_sh[0])[tid] = __float2bfloat16(p0);
    }

    // ---- prefetch first chunk's feats (rows 1..8) ----
    int c = 1;
    float fr0, fr1;
    {
        int r0 = min(c + r,     S_ - 1);
        int r1 = min(c + r + 4, S_ - 1);
        fr0 = fb[r0 * T_ + col];
        fr1 = fb[r1 * T_ + col];
    }
    __syncthreads();   // p_sh, redg visible

    // ---- forward recurrence ----
    int   cur    = 0;
    float logacc = 0.f;

    while (c < len) {
        // stage exp(f) for this chunk from prefetched regs
        f_sh[r][col]     = __expf(fr0);
        f_sh[r + 4][col] = __expf(fr1);

        // prefetch next chunk
        int nc = c + CHUNK;
        if (nc < S_) {
            int r0 = min(nc + r,     S_ - 1);
            int r1 = min(nc + r + 4, S_ - 1);
            fr0 = fb[r0 * T_ + col];
            fr1 = fb[r1 * T_ + col];
        }

        // renormalize: z = sum(p) via bf16 pair tree (exactly compensated below)
        float z;
        {
            const uint4* pv = (const uint4*)p_sh[cur];
            uint4 u0 = pv[0], u1 = pv[1], u2 = pv[2], u3 = pv[3];
            __nv_bfloat162 s0, s1, s2, s3;
            s0 = __hadd2(*(__nv_bfloat162*)&u0.x, *(__nv_bfloat162*)&u0.y);
            s0 = __hadd2(s0, __hadd2(*(__nv_bfloat162*)&u0.z, *(__nv_bfloat162*)&u0.w));
            s1 = __hadd2(*(__nv_bfloat162*)&u1.x, *(__nv_bfloat162*)&u1.y);
            s1 = __hadd2(s1, __hadd2(*(__nv_bfloat162*)&u1.z, *(__nv_bfloat162*)&u1.w));
            s2 = __hadd2(*(__nv_bfloat162*)&u2.x, *(__nv_bfloat162*)&u2.y);
            s2 = __hadd2(s2, __hadd2(*(__nv_bfloat162*)&u2.z, *(__nv_bfloat162*)&u2.w));
            s3 = __hadd2(*(__nv_bfloat162*)&u3.x, *(__nv_bfloat162*)&u3.y);
            s3 = __hadd2(s3, __hadd2(*(__nv_bfloat162*)&u3.z, *(__nv_bfloat162*)&u3.w));
            float2 t0 = __bfloat1622float2(__hadd2(s0, s1));
            float2 t1 = __bfloat1622float2(__hadd2(s2, s3));
            z = (t0.x + t0.y) + (t1.x + t1.y);
        }
        float scale = __fdividef(1.0f, z);
        logacc += __logf(z);

        const int cnt = min(CHUNK, len - c);
        __syncthreads();   // f_sh visible; all p reads done

        #pragma unroll
        for (int k = 0; k < CHUNK; ++k) {
            if (k >= cnt) break;   // uniform across block
            float fk = f_sh[k][j];
            // my seg slice: pairs [8*seg, 8*seg+8) = 32 bytes = 2 x LDS.128
            const uint4* pp = (const uint4*)(p_sh[cur] + seg * 8);
            uint4 u0 = pp[0], u1 = pp[1];
            __nv_bfloat162 a0, a1, a2, a3;
            a0 = __hmul2(*(__nv_bfloat162*)&u0.x, e2[0]);
            a1 = __hmul2(*(__nv_bfloat162*)&u0.y, e2[1]);
            a2 = __hmul2(*(__nv_bfloat162*)&u0.z, e2[2]);
            a3 = __hmul2(*(__nv_bfloat162*)&u0.w, e2[3]);
            a0 = __hfma2(*(__nv_bfloat162*)&u1.x, e2[4], a0);
            a1 = __hfma2(*(__nv_bfloat162*)&u1.y, e2[5], a1);
            a2 = __hfma2(*(__nv_bfloat162*)&u1.z, e2[6], a2);
            a3 = __hfma2(*(__nv_bfloat162*)&u1.w, e2[7], a3);
            __nv_bfloat162 s = __hadd2(__hadd2(a0, a1), __hadd2(a2, a3));
            float2 fv = __bfloat1622float2(s);
            float v = fv.x + fv.y;
            v += __shfl_xor_sync(0xffffffffu, v, 8);
            v += __shfl_xor_sync(0xffffffffu, v, 16);
            float q = v * fk;
            if (k == 0) q *= scale;
            if (seg == 0)
                ((__nv_bfloat16*)p_sh[cur ^ 1])[j] = __float2bfloat16(q);
            __syncthreads();
            cur ^= 1;
        }
        c += CHUNK;
    }

    // ---- final transition into END ----
    if (tid < T_) {
        float pv = __bfloat162float(((const __nv_bfloat16*)p_sh[cur])[tid]);
        float v = pv * __expf(trans_sh[tid * T_ + (T_ - 1)]);
        #pragma unroll
        for (int o = 16; o; o >>= 1) v += __shfl_xor_sync(0xffffffffu, v, o);
        if (lane == 0) redf[warp] = v;
    }
    __syncthreads();
    if (tid == 0) {
        float forward = logacc + __logf(redf[0] + redf[1]);
        float gold = 0.f;
        #pragma unroll
        for (int w = 0; w < 8; ++w) gold += redg[w];
        g_res[b] = forward - gold;
    }
}

__global__ void crf_reduce_kernel(float* __restrict__ out)
{
    const int tid  = threadIdx.x;
    const int lane = tid & 31;
    const int warp = tid >> 5;
    __shared__ float sh[2];

    float v = g_res[tid];
    #pragma unroll
    for (int o = 16; o; o >>= 1) v += __shfl_xor_sync(0xffffffffu, v, o);
    if (lane == 0) sh[warp] = v;
    __syncthreads();
    if (tid == 0) out[0] = sh[0] + sh[1];
}

extern "C" void kernel_launch(void* const* d_in, const int* in_sizes, int n_in,
                              void* d_out, int out_size)
{
    const float* feats = (const float*)d_in[0];
    const float* trans = (const float*)d_in[1];
    const int*   mask  = (const int*)d_in[2];
    const int*   tags  = (const int*)d_in[3];
    float* out = (float*)d_out;

    crf_forward_kernel<<<B_, 256>>>(feats, trans, mask, tags);
    crf_reduce_kernel<<<1, 64>>>(out);
}

// round 8
// speedup vs baseline: 2.3731x; 1.0618x over previous
#include <cuda_runtime.h>
#include <cuda_bf16.h>

// CRF NLL, prob-domain forward. B=64, S=512, T=64 (START=62, END=63).
// R8: R7 structure (256 thr, 4-way i-seg split, 2 SHFL, 1 bar/step) with
//     the ENTIRE post-matvec combine kept packed in bf16 (no F2F on the
//     critical path) and exact power-of-2 renorm (hmax2 exponent grab,
//     integer ksum) replacing z-sum + frcp + logf.
//
// Inputs: d_in[0] feats f32 [B,S,T], d_in[1] transitions f32 [T,T],
//         d_in[2] mask i32 [B,S] (contiguous prefix), d_in[3] tags i32 [B,S]
// Output: f32 scalar sum_b (forward_b - gold_b)

#define B_    64
#define S_    512
#define T_    64
#define CHUNK 8

__device__ float g_res[B_];

__global__ __launch_bounds__(256, 1) void crf_forward_kernel(
    const float* __restrict__ feats,
    const float* __restrict__ trans,
    const int*   __restrict__ mask,
    const int*   __restrict__ tags)
{
    __shared__ __align__(16) float trans_sh[T_ * T_];
    __shared__ __align__(16) __nv_bfloat162 p_sh[2][T_ / 2];   // 32 pairs
    __shared__ __align__(16) __nv_bfloat16  f_sh[CHUNK][T_];   // bf16 emissions
    __shared__ int   tags_sh[S_];
    __shared__ float redg[8];
    __shared__ float redf[2];
    __shared__ int   redi[8];

    const int b    = blockIdx.x;
    const int tid  = threadIdx.x;
    const int lane = tid & 31;
    const int warp = tid >> 5;
    const int seg  = lane >> 3;                 // 0..3 : i-segment of 16
    const int j    = (warp << 3) | (lane & 7);  // 0..63 : state column
    const int r    = tid >> 6;                  // 0..3 : staging row group
    const int col  = tid & 63;                  // staging column

    const float* fb    = feats + (size_t)b * S_ * T_;
    const int*   maskb = mask  + b * S_;
    const int*   tagsb = tags  + b * S_;

    // ---- stage transitions (coalesced float4) ----
    {
        const float4* t4 = (const float4*)trans;
        float4*       s4 = (float4*)trans_sh;
        #pragma unroll
        for (int i = 0; i < 4; ++i) s4[i * 256 + tid] = t4[i * 256 + tid];
    }
    // ---- tags + length ----
    int lenp = 0;
    #pragma unroll
    for (int k = 0; k < 2; ++k) {
        tags_sh[k * 256 + tid] = tagsb[k * 256 + tid];
        lenp += maskb[k * 256 + tid];
    }
    #pragma unroll
    for (int o = 16; o; o >>= 1) lenp += __shfl_xor_sync(0xffffffffu, lenp, o);
    if (lane == 0) redi[warp] = lenp;
    __syncthreads();
    int len = 0;
    #pragma unroll
    for (int w = 0; w < 8; ++w) len += redi[w];

    // ---- gold path score ----
    float g = 0.f;
    #pragma unroll
    for (int kk = 0; kk < 2; ++kk) {
        int s = kk * 256 + tid;
        if (s < len) {
            int tg = tags_sh[s];
            int pv = s ? tags_sh[s - 1] : (T_ - 2);
            g += fb[s * T_ + tg] + trans_sh[pv * T_ + tg];
        }
    }
    if (tid == 0) g += trans_sh[tags_sh[len - 1] * T_ + (T_ - 1)];
    #pragma unroll
    for (int o = 16; o; o >>= 1) g += __shfl_xor_sync(0xffffffffu, g, o);
    if (lane == 0) redg[warp] = g;

    // ---- E segment as bf16 pairs: e2[m] = (E[16s+2m][j], E[16s+2m+1][j]) ----
    __nv_bfloat162 e2[8];
    #pragma unroll
    for (int m = 0; m < 8; ++m) {
        int i0 = seg * 16 + 2 * m;
        float x = __expf(trans_sh[i0 * T_ + j]);
        float y = __expf(trans_sh[(i0 + 1) * T_ + j]);
        e2[m] = __floats2bfloat162_rn(x, y);
    }

    // ---- init p_0 (bf16 state) ----
    if (tid < T_) {
        float p0 = __expf(fb[tid] + trans_sh[(T_ - 2) * T_ + tid]);
        ((__nv_bfloat16*)p_sh[0])[tid] = __float2bfloat16(p0);
    }

    // ---- prefetch first chunk's feats (rows 1..8) ----
    int c = 1;
    float fr0, fr1;
    {
        int r0 = min(c + r,     S_ - 1);
        int r1 = min(c + r + 4, S_ - 1);
        fr0 = fb[r0 * T_ + col];
        fr1 = fb[r1 * T_ + col];
    }
    __syncthreads();   // p_sh, redg visible

    // ---- forward recurrence ----
    int cur  = 0;
    int ksum = 0;

    while (c < len) {
        // stage exp(f) for this chunk as bf16 (off critical path)
        f_sh[r][col]     = __float2bfloat16(__expf(fr0));
        f_sh[r + 4][col] = __float2bfloat16(__expf(fr1));

        // prefetch next chunk
        int nc = c + CHUNK;
        if (nc < S_) {
            int r0 = min(nc + r,     S_ - 1);
            int r1 = min(nc + r + 4, S_ - 1);
            fr0 = fb[r0 * T_ + col];
            fr1 = fb[r1 * T_ + col];
        }

        // exact power-of-2 renorm: k = exponent of max(p) (redundant per-thread)
        __nv_bfloat16 scale_h;
        {
            const uint4* pv = (const uint4*)p_sh[cur];
            uint4 u0 = pv[0], u1 = pv[1], u2 = pv[2], u3 = pv[3];
            __nv_bfloat162 m0, m1, m2, m3;
            m0 = __hmax2(*(__nv_bfloat162*)&u0.x, *(__nv_bfloat162*)&u0.y);
            m0 = __hmax2(m0, __hmax2(*(__nv_bfloat162*)&u0.z, *(__nv_bfloat162*)&u0.w));
            m1 = __hmax2(*(__nv_bfloat162*)&u1.x, *(__nv_bfloat162*)&u1.y);
            m1 = __hmax2(m1, __hmax2(*(__nv_bfloat162*)&u1.z, *(__nv_bfloat162*)&u1.w));
            m2 = __hmax2(*(__nv_bfloat162*)&u2.x, *(__nv_bfloat162*)&u2.y);
            m2 = __hmax2(m2, __hmax2(*(__nv_bfloat162*)&u2.z, *(__nv_bfloat162*)&u2.w));
            m3 = __hmax2(*(__nv_bfloat162*)&u3.x, *(__nv_bfloat162*)&u3.y);
            m3 = __hmax2(m3, __hmax2(*(__nv_bfloat162*)&u3.z, *(__nv_bfloat162*)&u3.w));
            __nv_bfloat162 mm = __hmax2(__hmax2(m0, m1), __hmax2(m2, m3));
            __nv_bfloat16  mx = __hmax(__low2bfloat16(mm), __high2bfloat16(mm));
            unsigned short bits = *(unsigned short*)&mx;
            int ke = ((bits >> 7) & 0xFF) - 127;
            ksum += ke;
            unsigned short sb = (unsigned short)((127 - ke) << 7);  // 2^-ke
            scale_h = *(__nv_bfloat16*)&sb;
        }

        const int cnt = min(CHUNK, len - c);
        __syncthreads();   // f_sh visible; all p reads done

        #pragma unroll
        for (int k = 0; k < CHUNK; ++k) {
            if (k >= cnt) break;   // uniform across block
            __nv_bfloat16 fk = f_sh[k][j];
            // my seg slice: pairs [8*seg, 8*seg+8) = 32 bytes = 2 x LDS.128
            const uint4* pp = (const uint4*)(p_sh[cur] + seg * 8);
            uint4 u0 = pp[0], u1 = pp[1];
            __nv_bfloat162 a0, a1, a2, a3;
            a0 = __hmul2(*(__nv_bfloat162*)&u0.x, e2[0]);
            a1 = __hmul2(*(__nv_bfloat162*)&u0.y, e2[1]);
            a2 = __hmul2(*(__nv_bfloat162*)&u0.z, e2[2]);
            a3 = __hmul2(*(__nv_bfloat162*)&u0.w, e2[3]);
            a0 = __hfma2(*(__nv_bfloat162*)&u1.x, e2[4], a0);
            a1 = __hfma2(*(__nv_bfloat162*)&u1.y, e2[5], a1);
            a2 = __hfma2(*(__nv_bfloat162*)&u1.z, e2[6], a2);
            a3 = __hfma2(*(__nv_bfloat162*)&u1.w, e2[7], a3);
            __nv_bfloat162 s = __hadd2(__hadd2(a0, a1), __hadd2(a2, a3));
            // packed cross-seg combine (no F2F): shfl u32 + hadd2
            unsigned su = *(unsigned*)&s;
            unsigned t1 = __shfl_xor_sync(0xffffffffu, su, 8);
            s = __hadd2(s, *(__nv_bfloat162*)&t1);
            su = *(unsigned*)&s;
            unsigned t2 = __shfl_xor_sync(0xffffffffu, su, 16);
            s = __hadd2(s, *(__nv_bfloat162*)&t2);
            __nv_bfloat16 h = __hadd(__low2bfloat16(s), __high2bfloat16(s));
            __nv_bfloat16 q = __hmul(h, fk);
            if (k == 0) q = __hmul(q, scale_h);   // exact power of 2
            if (seg == 0)
                ((__nv_bfloat16*)p_sh[cur ^ 1])[j] = q;
            __syncthreads();
            cur ^= 1;
        }
        c += CHUNK;
    }

    // ---- final transition into END ----
    if (tid < T_) {
        float pv = __bfloat162float(((const __nv_bfloat16*)p_sh[cur])[tid]);
        float v = pv * __expf(trans_sh[tid * T_ + (T_ - 1)]);
        #pragma unroll
        for (int o = 16; o; o >>= 1) v += __shfl_xor_sync(0xffffffffu, v, o);
        if (lane == 0) redf[warp] = v;
    }
    __syncthreads();
    if (tid == 0) {
        float forward = (float)ksum * 0.69314718055994531f
                        + __logf(redf[0] + redf[1]);
        float gold = 0.f;
        #pragma unroll
        for (int w = 0; w < 8; ++w) gold += redg[w];
        g_res[b] = forward - gold;
    }
}

__global__ void crf_reduce_kernel(float* __restrict__ out)
{
    const int tid  = threadIdx.x;
    const int lane = tid & 31;
    const int warp = tid >> 5;
    __shared__ float sh[2];

    float v = g_res[tid];
    #pragma unroll
    for (int o = 16; o; o >>= 1) v += __shfl_xor_sync(0xffffffffu, v, o);
    if (lane == 0) sh[warp] = v;
    __syncthreads();
    if (tid == 0) out[0] = sh[0] + sh[1];
}

extern "C" void kernel_launch(void* const* d_in, const int* in_sizes, int n_in,
                              void* d_out, int out_size)
{
    const float* feats = (const float*)d_in[0];
    const float* trans = (const float*)d_in[1];
    const int*   mask  = (const int*)d_in[2];
    const int*   tags  = (const int*)d_in[3];
    float* out = (float*)d_out;

    crf_forward_kernel<<<B_, 256>>>(feats, trans, mask, tags);
    crf_reduce_kernel<<<1, 64>>>(out);
}